// round 17
// baseline (speedup 1.0000x reference)
#include <cuda_runtime.h>
#include <cuda_bf16.h>
#include <math.h>
#include <stdint.h>

// ---------------- problem constants ----------------
#define NN    8192
#define KNB   32
#define CLd   384
#define CPd   128
#define Hh    4
#define Sd    32
#define Pp    8
#define PROJ  336
#define NPAD  384
#define CONC  736
#define KP2   768

// ---------------- scratch (device globals; no allocation) ----------------
__device__ __align__(16) float g_Atf[NN * CLd];      // tf32-rounded local
__device__ __align__(16) float g_WpT[NPAD * CLd];    // tf32-rounded Wproj^T (padded)
__device__ __align__(16) float g_biasp[NPAD];
__device__ __align__(16) float g_WoT[NPAD * KP2];    // tf32-rounded Wout^T (padded)
__device__ __align__(16) float g_C[NN * KP2];        // tf32-rounded concat
__device__ __align__(16) float g_proj[NN * NPAD];
__device__ __align__(16) float g_q [NN * 128];
__device__ __align__(16) float g_k [NN * 32];
__device__ __align__(16) float g_v [NN * 32];
__device__ __align__(16) float g_qp[NN * 96];
__device__ __align__(16) float g_kp[NN * 24];
__device__ __align__(16) float g_vp[NN * 24];

// ---------------- PTX helpers ----------------
__device__ __forceinline__ uint32_t smem_u32(const void* p) {
    uint32_t a;
    asm("{ .reg .u64 t; cvta.to.shared.u64 t, %1; cvt.u32.u64 %0, t; }" : "=r"(a) : "l"(p));
    return a;
}
__device__ __forceinline__ float to_tf32(float x) {
    float r;
    asm("cvt.rna.tf32.f32 %0, %1;" : "=f"(r) : "f"(x));
    return r;
}

#define CP16(dst, src) \
    asm volatile("cp.async.cg.shared.global [%0], [%1], 16;" :: "r"(dst), "l"(src))
#define CP_COMMIT() asm volatile("cp.async.commit_group;" ::: "memory")
#define CP_WAIT(n)  asm volatile("cp.async.wait_group %0;" :: "n"(n) : "memory")

#define LDSM4(R, addr) \
    asm volatile("ldmatrix.sync.aligned.m8n8.x4.shared.b16 {%0,%1,%2,%3}, [%4];" \
        : "=r"((R)[0]), "=r"((R)[1]), "=r"((R)[2]), "=r"((R)[3]) : "r"(addr))

#define MMATF32(C, A, b0, b1) \
    asm volatile("mma.sync.aligned.m16n8k8.row.col.f32.tf32.tf32.f32 " \
        "{%0,%1,%2,%3}, {%4,%5,%6,%7}, {%8,%9}, {%0,%1,%2,%3};" \
        : "+f"((C)[0]), "+f"((C)[1]), "+f"((C)[2]), "+f"((C)[3]) \
        : "r"((A)[0]), "r"((A)[1]), "r"((A)[2]), "r"((A)[3]), "r"(b0), "r"(b1))

// ---------------- misc warp helpers ----------------
__device__ __forceinline__ float warp_sum(float v) {
#pragma unroll
    for (int o = 16; o; o >>= 1) v += __shfl_xor_sync(0xffffffffu, v, o);
    return v;
}
__device__ __forceinline__ float warp_max(float v) {
#pragma unroll
    for (int o = 16; o; o >>= 1) v = fmaxf(v, __shfl_xor_sync(0xffffffffu, v, o));
    return v;
}
__device__ __forceinline__ float2 warp_sum2(float a, float b) {
#pragma unroll
    for (int o = 16; o; o >>= 1) {
        a += __shfl_xor_sync(0xffffffffu, a, o);
        b += __shfl_xor_sync(0xffffffffu, b, o);
    }
    return make_float2(a, b);
}

// ---------------- fused prep kernel ----------------
#define WPT_TILES 144          // 12 x 12
#define WOT_TILES 288          // 12 x 24
#define LOCAL_BLKS 2048
#define PREP_GRID (WPT_TILES + WOT_TILES + LOCAL_BLKS)

__global__ void __launch_bounds__(256) prep_fused(
    const float* __restrict__ local,
    const float* __restrict__ Wq,  const float* __restrict__ bq,
    const float* __restrict__ Wk,  const float* __restrict__ bk,
    const float* __restrict__ Wv,  const float* __restrict__ bv,
    const float* __restrict__ Wqp, const float* __restrict__ bqp,
    const float* __restrict__ Wkp, const float* __restrict__ bkp,
    const float* __restrict__ Wvp, const float* __restrict__ bvp,
    const float* __restrict__ Wout)
{
    __shared__ float tile[32][33];
    const int b  = blockIdx.x;
    const int tx = threadIdx.x & 31;
    const int ty = threadIdx.x >> 5;

    if (b < WPT_TILES) {
        const int n0 = (b % 12) * 32, k0 = (b / 12) * 32;
#pragma unroll
        for (int i = 0; i < 4; i++) {
            int k = k0 + ty + i * 8, n = n0 + tx;
            float w = 0.f;
            if      (n < 128) w = Wq [k * 128 + n];
            else if (n < 160) w = Wk [k * 32  + (n - 128)];
            else if (n < 192) w = Wv [k * 32  + (n - 160)];
            else if (n < 288) w = Wqp[k * 96  + (n - 192)];
            else if (n < 312) w = Wkp[k * 24  + (n - 288)];
            else if (n < 336) w = Wvp[k * 24  + (n - 312)];
            tile[ty + i * 8][tx] = w;
        }
        __syncthreads();
#pragma unroll
        for (int i = 0; i < 4; i++) {
            int n = n0 + ty + i * 8, k = k0 + tx;
            g_WpT[(size_t)n * CLd + k] = to_tf32(tile[tx][ty + i * 8]);
        }
    } else if (b < WPT_TILES + WOT_TILES) {
        const int bb = b - WPT_TILES;
        const int n0 = (bb % 12) * 32, k0 = (bb / 12) * 32;
#pragma unroll
        for (int i = 0; i < 4; i++) {
            int k = k0 + ty + i * 8, n = n0 + tx;
            float w = (k < CONC) ? Wout[(size_t)k * CLd + n] : 0.f;
            tile[ty + i * 8][tx] = w;
        }
        __syncthreads();
#pragma unroll
        for (int i = 0; i < 4; i++) {
            int n = n0 + ty + i * 8, k = k0 + tx;
            g_WoT[(size_t)n * KP2 + k] = to_tf32(tile[tx][ty + i * 8]);
        }
    } else {
        const int lb = b - WPT_TILES - WOT_TILES;
        const int t  = threadIdx.x;
        const int total = NN * CLd;
        for (int idx = lb * 256 + t; idx < total; idx += LOCAL_BLKS * 256)
            g_Atf[idx] = to_tf32(local[idx]);
        if (lb == 0 && t < NPAD) {
            int n = t;
            float bias = 0.f;
            if      (n < 128) bias = bq [n];
            else if (n < 160) bias = bk [n - 128];
            else if (n < 192) bias = bv [n - 160];
            else if (n < 288) bias = bqp[n - 192];
            else if (n < 312) bias = bkp[n - 288];
            else if (n < 336) bias = bvp[n - 312];
            g_biasp[n] = bias;
        }
    }
}

// ---------------- tf32 HMMA GEMM ----------------
#define TSTG_BYTES 87040
#define TOFF_B 34816
#define TGEMM_SMEM (2 * TSTG_BYTES)

__device__ __forceinline__ void issue_tile_f32(uint32_t sdst, const float* __restrict__ src,
                                               int K, int kk, int tid, int nchunks)
{
#pragma unroll
    for (int i = tid; i < nchunks; i += 512) {
        int r = i >> 4, c = i & 15;
        CP16(sdst + r * 272 + c * 16, src + (size_t)r * K + kk + c * 4);
    }
}

__global__ void __launch_bounds__(512, 1) mma_gemm(
    const float* __restrict__ A,
    const float* __restrict__ B,
    const float* __restrict__ bias, float* __restrict__ C, int K)
{
    extern __shared__ char dsm[];
    const uint32_t sbase = smem_u32(dsm);
    const int tid  = threadIdx.x;
    const int lane = tid & 31;
    const int wid  = tid >> 5;
    const int wm   = wid >> 2;
    const int wn   = wid & 3;
    const int rowBase = blockIdx.y * 128;
    const int colBase = blockIdx.x * 192;
    const int NC = K >> 6;

    const float* pA = A + (size_t)rowBase * K;
    const float* pB = B + (size_t)colBase * K;

    const uint32_t aoff = (uint32_t)((lane & 15) * 272 + ((lane >> 4) << 4));
    const uint32_t boff = (uint32_t)((((lane >> 4) * 8 + (lane & 7)) * 272) + (((lane >> 3) & 1) << 4));
    const uint32_t awbase = (uint32_t)(wm * 32 * 272);
    const uint32_t bwbase = (uint32_t)(wn * 48 * 272);

    float acc[2][6][4];
#pragma unroll
    for (int i = 0; i < 2; i++)
#pragma unroll
        for (int j = 0; j < 6; j++)
#pragma unroll
            for (int q = 0; q < 4; q++) acc[i][j][q] = 0.f;

    issue_tile_f32(sbase,          pA, K, 0, tid, 2048);
    issue_tile_f32(sbase + TOFF_B, pB, K, 0, tid, 3072);
    CP_COMMIT();

    for (int i = 0; i < NC; i++) {
        if (i + 1 < NC) {
            uint32_t st = sbase + (uint32_t)((i + 1) & 1) * TSTG_BYTES;
            int kk = (i + 1) << 6;
            issue_tile_f32(st,          pA, K, kk, tid, 2048);
            issue_tile_f32(st + TOFF_B, pB, K, kk, tid, 3072);
            CP_COMMIT();
            CP_WAIT(1);
        } else {
            CP_WAIT(0);
        }
        __syncthreads();

        const uint32_t st = sbase + (uint32_t)(i & 1) * TSTG_BYTES;
        const uint32_t sA = st + awbase;
        const uint32_t sB = st + TOFF_B + bwbase;

#pragma unroll
        for (int s = 0; s < 8; s++) {
            const uint32_t ka = (uint32_t)(s * 32);
            uint32_t av[8], bv[12];
            LDSM4(av,     sA + ka + aoff);
            LDSM4(av + 4, sA + 16 * 272 + ka + aoff);
#pragma unroll
            for (int L = 0; L < 3; L++)
                LDSM4(bv + L * 4, sB + (uint32_t)(L * 16 * 272) + ka + boff);
#pragma unroll
            for (int mf = 0; mf < 2; mf++) {
#pragma unroll
                for (int nt = 0; nt < 6; nt++) {
                    const int L = nt >> 1, h = (nt & 1) * 2;
                    MMATF32(acc[mf][nt], av + mf * 4, bv[L * 4 + h], bv[L * 4 + h + 1]);
                }
            }
        }
        __syncthreads();
    }

    const int r0 = lane >> 2;
    const int c0 = (lane & 3) * 2;
#pragma unroll
    for (int mf = 0; mf < 2; mf++) {
#pragma unroll
        for (int nt = 0; nt < 6; nt++) {
            int row = rowBase + wm * 32 + mf * 16 + r0;
            int col = colBase + wn * 48 + nt * 8 + c0;
            float b0 = 0.f, b1 = 0.f;
            if (bias) { b0 = bias[col]; b1 = bias[col + 1]; }
            float2 v0 = make_float2(acc[mf][nt][0] + b0, acc[mf][nt][1] + b1);
            float2 v1 = make_float2(acc[mf][nt][2] + b0, acc[mf][nt][3] + b1);
            *(float2*)(C + (size_t)row * NPAD + col)       = v0;
            *(float2*)(C + (size_t)(row + 8) * NPAD + col) = v1;
        }
    }
}

// ---------------- kernel: LN + frame transforms (4 warps / node, 2 nodes / block) ----------
__global__ void __launch_bounds__(256) proj_epilogue(const float* __restrict__ frames)
{
    const int warp = threadIdx.x >> 5;   // 0..7
    const int lane = threadIdx.x & 31;
    const int n = blockIdx.x * 2 + (warp >> 2);
    const int j = warp & 3;              // sub-task within node
    const float* pr = g_proj + (size_t)n * NPAD;
    const float inv_sqrtS = 0.17677669529663687f;

    // q head j LN (all 4 warps, one head each)
    {
        float x  = pr[j * 32 + lane];
        float2 s = warp_sum2(x, x * x);
        float mu = s.x * (1.f / 32.f);
        float var = s.y * (1.f / 32.f) - mu * mu;
        g_q[(size_t)n * 128 + j * 32 + lane] = (x - mu) * rsqrtf(var + 1e-5f) * inv_sqrtS;
    }

    if (j == 0) {
        // k LN
        float x  = pr[128 + lane];
        float2 s = warp_sum2(x, x * x);
        float mu = s.x * (1.f / 32.f);
        float var = s.y * (1.f / 32.f) - mu * mu;
        g_k[(size_t)n * 32 + lane] = (x - mu) * rsqrtf(var + 1e-5f);
    } else if (j == 1) {
        // v copy
        g_v[(size_t)n * 32 + lane] = pr[160 + lane];
    } else if (j == 2) {
        // qp transform (32 points, lane = point)
        const float* fr = frames + (size_t)n * 16;
        float R00 = fr[0],  R01 = fr[1],  R02 = fr[2],  t0 = fr[3];
        float R10 = fr[4],  R11 = fr[5],  R12 = fr[6],  t1 = fr[7];
        float R20 = fr[8],  R21 = fr[9],  R22 = fr[10], t2 = fr[11];
        float px = pr[192 + lane * 3 + 0];
        float py = pr[192 + lane * 3 + 1];
        float pz = pr[192 + lane * 3 + 2];
        float* q = g_qp + (size_t)n * 96 + lane * 3;
        q[0] = R00 * px + R01 * py + R02 * pz + t0;
        q[1] = R10 * px + R11 * py + R12 * pz + t1;
        q[2] = R20 * px + R21 * py + R22 * pz + t2;
    } else {
        // kp (lanes 0-7), vp (lanes 8-15)
        const float* fr = frames + (size_t)n * 16;
        float R00 = fr[0],  R01 = fr[1],  R02 = fr[2],  t0 = fr[3];
        float R10 = fr[4],  R11 = fr[5],  R12 = fr[6],  t1 = fr[7];
        float R20 = fr[8],  R21 = fr[9],  R22 = fr[10], t2 = fr[11];
        if (lane < 8) {
            float px = pr[288 + lane * 3 + 0];
            float py = pr[288 + lane * 3 + 1];
            float pz = pr[288 + lane * 3 + 2];
            float* q = g_kp + (size_t)n * 24 + lane * 3;
            q[0] = R00 * px + R01 * py + R02 * pz + t0;
            q[1] = R10 * px + R11 * py + R12 * pz + t1;
            q[2] = R20 * px + R21 * py + R22 * pz + t2;
        } else if (lane < 16) {
            int l2 = lane - 8;
            float px = pr[312 + l2 * 3 + 0];
            float py = pr[312 + l2 * 3 + 1];
            float pz = pr[312 + l2 * 3 + 2];
            float* q = g_vp + (size_t)n * 24 + l2 * 3;
            q[0] = R00 * px + R01 * py + R02 * pz + t0;
            q[1] = R10 * px + R11 * py + R12 * pz + t1;
            q[2] = R20 * px + R21 * py + R22 * pz + t2;
        }
    }
}

// ---------------- kernel: attention (R16 + Wb-in-registers via shfl) ----------------
__global__ void __launch_bounds__(128, 7) attn_kernel(
    const float* __restrict__ pair,        // N*K*CP
    const int*   __restrict__ neighbours,  // N*K
    const float* __restrict__ frames,      // N*16
    const float* __restrict__ Wb,          // CP*H
    const float* __restrict__ gamma)       // H
{
    const int n    = blockIdx.x;
    const int t    = threadIdx.x;
    const int lane = t & 31;
    const int warp = t >> 5;

    __shared__ __align__(16) float s_q[128];
    __shared__ __align__(16) float s_qp[96];
    __shared__ int   s_nb[32];
    __shared__ __align__(16) float s_k [32][36];
    __shared__ __align__(16) float s_kp[32][28];
    __shared__ __align__(16) float s_pair[32 * 128];
    __shared__ __align__(16) float s_WbT[4 * 128];
    __shared__ __align__(16) float s_pb2[2 * 128];    // [half][k*4+h]
    __shared__ __align__(16) float s_attnT[32 * 4];   // [k][h]
    __shared__ float s_pt[96];

    // async pair load (16KB) — overlaps gathers
    {
        const uint32_t sp = smem_u32(s_pair);
        const float* psrc = pair + (size_t)n * 4096;
#pragma unroll
        for (int j = 0; j < 8; j++) {
            int i = t + 128 * j;
            CP16(sp + (uint32_t)i * 16, psrc + i * 4);
        }
        CP_COMMIT();
    }

    if (t < 32) s_nb[t] = neighbours[(size_t)n * 32 + t];
    s_q[t] = g_q[(size_t)n * 128 + t];
    if (t < 96) s_qp[t] = g_qp[(size_t)n * 96 + t];
    for (int i = t; i < 512; i += 128) {
        int c = i & 127, h = i >> 7;
        s_WbT[h * 128 + c] = Wb[c * 4 + h];
    }
    __syncthreads();   // s_nb ready

    // k gather
#pragma unroll
    for (int i = t; i < 256; i += 128) {
        int row = i >> 3, c4 = i & 7, nb = s_nb[row];
        float4 kv = *(const float4*)(g_k + (size_t)nb * 32 + c4 * 4);
        *(float4*)(&s_k[row][c4 * 4]) = kv;
    }
    // kp gather
#pragma unroll
    for (int i = t; i < 192; i += 128) {
        int row = i / 6, c4 = i % 6, nb = s_nb[row];
        float4 a4 = *(const float4*)(g_kp + (size_t)nb * 24 + c4 * 4);
        *(float4*)(&s_kp[row][c4 * 4]) = a4;
    }
    CP_WAIT(0);
    __syncthreads();

    // pb partials: warp w -> heads {h0, h0+1}, column half [64*(w&1), +64).
    // Wb strip cached in registers (lane i holds chunk i); rotated access via shfl
    // => zero LDS wavefronts for Wb (was 512/block).
    {
        const int half = warp & 1;
        const int h0   = (warp >> 1) << 1;
        const float4* prow = (const float4*)(s_pair + lane * 128 + half * 64);
        const float4 w0 = ((const float4*)(s_WbT + (h0 + 0) * 128 + half * 64))[lane & 15];
        const float4 w1 = ((const float4*)(s_WbT + (h0 + 1) * 128 + half * 64))[lane & 15];
        float pp0 = 0.f, pp1 = 0.f;
#pragma unroll 4
        for (int i = 0; i < 16; i++) {
            int rot = (i + lane) & 15;
            float4 p = prow[rot];
            float wax = __shfl_sync(0xffffffffu, w0.x, rot);
            float way = __shfl_sync(0xffffffffu, w0.y, rot);
            float waz = __shfl_sync(0xffffffffu, w0.z, rot);
            float waw = __shfl_sync(0xffffffffu, w0.w, rot);
            float wbx = __shfl_sync(0xffffffffu, w1.x, rot);
            float wby = __shfl_sync(0xffffffffu, w1.y, rot);
            float wbz = __shfl_sync(0xffffffffu, w1.z, rot);
            float wbw = __shfl_sync(0xffffffffu, w1.w, rot);
            pp0 += p.x * wax + p.y * way + p.z * waz + p.w * waw;
            pp1 += p.x * wbx + p.y * wby + p.z * wbz + p.w * wbw;
        }
        *(float2*)(s_pb2 + half * 128 + lane * 4 + h0) = make_float2(pp0, pp1);
    }
    __syncthreads();

    // ---- logits: head = warp, neighbour = lane ----
    const float w_L = 0.5773502691896258f;
    float gam   = gamma[warp];
    float scale = log1pf(__expf(gam)) * (1.0f / 6.0f) * 0.5f;

    // qk: float4 (proven safe in R15)
    float qk = 0.f;
    {
        const float4* qrow = (const float4*)(s_q + warp * 32);
        const float4* krow = (const float4*)(&s_k[lane][0]);
#pragma unroll
        for (int c4 = 0; c4 < 8; c4++) {
            float4 qv = qrow[c4], kv = krow[c4];
            qk += qv.x * kv.x + qv.y * kv.y + qv.z * kv.z + qv.w * kv.w;
        }
    }

    // dist: float4 under unroll-1 guard (R10 spill lesson)
    float dist = 0.f;
    {
        const float4* kpr = (const float4*)(&s_kp[lane][0]);
        const float4* qpr = (const float4*)(s_qp + warp * 24);
#pragma unroll 1
        for (int c4 = 0; c4 < 6; c4++) {
            float4 a = qpr[c4], b = kpr[c4];
            float dx = a.x - b.x, dy = a.y - b.y, dz = a.z - b.z, dw = a.w - b.w;
            dist += dx * dx + dy * dy + dz * dz + dw * dw;
        }
    }

    float pb = s_pb2[lane * 4 + warp] + s_pb2[128 + lane * 4 + warp];

    float logit = w_L * (qk - scale * dist + pb);
    float m = warp_max(logit);
    float e = __expf(logit - m);
    float sm = warp_sum(e);
    s_attnT[lane * 4 + warp] = e / sm;    // [k][h]
    __syncthreads();

    float* conc = g_C + (size_t)n * KP2;

    // local_up
    {
        float acc = 0.f;
#pragma unroll
        for (int kk = 0; kk < 32; kk++)
            acc += s_attnT[kk * 4 + warp] * __ldg(g_v + (size_t)s_nb[kk] * 32 + lane);
        conc[warp * 32 + lane] = to_tf32(acc);
    }
    // pair_up (transposed): thread = column t, 4 heads
    {
        float a0 = 0.f, a1 = 0.f, a2 = 0.f, a3 = 0.f;
#pragma unroll
        for (int kk = 0; kk < 32; kk++) {
            float4 a4 = *(const float4*)(s_attnT + kk * 4);   // broadcast
            float pv = s_pair[kk * 128 + t];
            a0 += a4.x * pv; a1 += a4.y * pv; a2 += a4.z * pv; a3 += a4.w * pv;
        }
        conc[128 + 0 * 128 + t] = to_tf32(a0);
        conc[128 + 1 * 128 + t] = to_tf32(a1);
        conc[128 + 2 * 128 + t] = to_tf32(a2);
        conc[128 + 3 * 128 + t] = to_tf32(a3);
    }
    // pt sums
    if (t < 96) {
        int h = t / 24, j = t % 24;
        float acc = 0.f;
#pragma unroll
        for (int kk = 0; kk < 32; kk++)
            acc += s_attnT[kk * 4 + h] * __ldg(g_vp + (size_t)s_nb[kk] * 24 + j);
        s_pt[t] = acc;
    }
    if (t < 32) conc[736 + t] = 0.f;   // zero K-padding
    __syncthreads();
    if (t < 96) {
        int h = t / 24, pj = (t % 24) / 3, aidx = t % 3;
        const float* fr = frames + (size_t)n * 16;
        float r0 = fr[0 * 4 + aidx], r1 = fr[1 * 4 + aidx], r2 = fr[2 * 4 + aidx];
        float v0 = s_pt[h * 24 + pj * 3 + 0] - fr[0 * 4 + 3];
        float v1 = s_pt[h * 24 + pj * 3 + 1] - fr[1 * 4 + 3];
        float v2 = s_pt[h * 24 + pj * 3 + 2] - fr[2 * 4 + 3];
        conc[640 + t] = to_tf32(r0 * v0 + r1 * v1 + r2 * v2);
    }
}

// ---------------- launch ----------------
extern "C" void kernel_launch(void* const* d_in, const int* in_sizes, int n_in,
                              void* d_out, int out_size)
{
    const float* local      = (const float*)d_in[0];
    const float* pair       = (const float*)d_in[1];
    const float* frames     = (const float*)d_in[2];
    const int*   neighbours = (const int*)  d_in[3];
    // d_in[4] = mask (all-true by construction; identity)
    const float* Wq  = (const float*)d_in[5];
    const float* bq  = (const float*)d_in[6];
    const float* Wk  = (const float*)d_in[7];
    const float* bk  = (const float*)d_in[8];
    const float* Wv  = (const float*)d_in[9];
    const float* bv  = (const float*)d_in[10];
    const float* Wqp = (const float*)d_in[11];
    const float* bqp = (const float*)d_in[12];
    const float* Wkp = (const float*)d_in[13];
    const float* bkp = (const float*)d_in[14];
    const float* Wvp = (const float*)d_in[15];
    const float* bvp = (const float*)d_in[16];
    const float* Wb  = (const float*)d_in[17];
    const float* gamma = (const float*)d_in[18];
    const float* Wout  = (const float*)d_in[19];
    float* out = (float*)d_out;

    void *p_Atf, *p_WpT, *p_bias, *p_WoT, *p_C, *p_proj;
    cudaGetSymbolAddress(&p_Atf, g_Atf);
    cudaGetSymbolAddress(&p_WpT, g_WpT);
    cudaGetSymbolAddress(&p_bias, g_biasp);
    cudaGetSymbolAddress(&p_WoT, g_WoT);
    cudaGetSymbolAddress(&p_C, g_C);
    cudaGetSymbolAddress(&p_proj, g_proj);

    cudaFuncSetAttribute(mma_gemm, cudaFuncAttributeMaxDynamicSharedMemorySize, TGEMM_SMEM);

    // 0) fused prep: weight transposes + local tf32 + bias (one launch)
    prep_fused<<<PREP_GRID, 256>>>(local, Wq, bq, Wk, bk, Wv, bv,
                                   Wqp, bqp, Wkp, bkp, Wvp, bvp, Wout);

    // 1) proj = local @ Wproj + bias   (K=384, NC=6)
    mma_gemm<<<dim3(2, 64), 512, TGEMM_SMEM>>>(
        (const float*)p_Atf, (const float*)p_WpT,
        (const float*)p_bias, (float*)p_proj, CLd);

    // 2) LN + frame transforms (4 warps/node, 2 nodes/block)
    proj_epilogue<<<NN / 2, 256>>>(frames);

    // 3) attention -> tf32 concat
    attn_kernel<<<NN, 128>>>(pair, neighbours, frames, Wb, gamma);

    // 4) out = concat @ Wout   (K=768, NC=12)
    mma_gemm<<<dim3(2, 64), 512, TGEMM_SMEM>>>(
        (const float*)p_C, (const float*)p_WoT,
        nullptr, out, KP2);
}